// round 1
// baseline (speedup 1.0000x reference)
#include <cuda_runtime.h>
#include <math.h>

#define M_BATCH 256
#define R_DIM   1025
#define C_DIM   1024

// Scratch (allowed: __device__ globals, no allocation)
__device__ __align__(16) float  g_G[M_BATCH * C_DIM];   // X1 @ mu
__device__ double g_mu2[256];
__device__ double g_lv[4];   // Svr=sum exp(lv_in), Slr=sum lv_in, Svc=sum exp(lv_out), Slc=sum lv_out

// ---------------------------------------------------------------------------
// Kernel 1: D_KL partial sums (deterministic: fixed partition, no atomics)
// ---------------------------------------------------------------------------
__global__ void dkl_partial_kernel(const float* __restrict__ mu,
                                   const float* __restrict__ lv_in,
                                   const float* __restrict__ lv_out) {
    __shared__ double red[256];
    const int t = threadIdx.x;
    const int b = blockIdx.x;
    const int total = R_DIM * C_DIM;

    double s = 0.0;
    for (int idx = b * 256 + t; idx < total; idx += 256 * 256) {
        float v = mu[idx];
        s += (double)v * (double)v;
    }
    red[t] = s;
    __syncthreads();
    for (int w = 128; w > 0; w >>= 1) {
        if (t < w) red[t] += red[t + w];
        __syncthreads();
    }
    if (t == 0) g_mu2[b] = red[0];

    if (b == 0) {
        double vals[4] = {0.0, 0.0, 0.0, 0.0};
        for (int i = t; i < R_DIM; i += 256) {
            float l = lv_in[i];
            vals[0] += exp((double)l);
            vals[1] += (double)l;
        }
        for (int i = t; i < C_DIM; i += 256) {
            float l = lv_out[i];
            vals[2] += exp((double)l);
            vals[3] += (double)l;
        }
        for (int j = 0; j < 4; j++) {
            __syncthreads();
            red[t] = vals[j];
            __syncthreads();
            for (int w = 128; w > 0; w >>= 1) {
                if (t < w) red[t] += red[t + w];
                __syncthreads();
            }
            if (t == 0) g_lv[j] = red[0];
        }
    }
}

// ---------------------------------------------------------------------------
// Kernel 2: G = X1 @ mu   (X1 = [x | ones], 256x1025 @ 1025x1024)
// Classic tiled GEMM, 64x64 tile, BK=8, 256 threads, 4x4 microtile.
// mu is read exactly once from DRAM (4.2 MB); x is L2-resident (1 MB).
// ---------------------------------------------------------------------------
#define BM 64
#define BN 64
#define BK 8

__global__ __launch_bounds__(256) void gemm_kernel(const float* __restrict__ x,
                                                   const float* __restrict__ mu) {
    __shared__ float As[BK][BM];
    __shared__ float Bs[BK][BN];

    const int tid = threadIdx.x;
    const int tx = tid & 15;         // 0..15 -> N
    const int ty = tid >> 4;         // 0..15 -> M
    const int bn0 = blockIdx.x * BN;
    const int bm0 = blockIdx.y * BM;

    float c[4][4];
    #pragma unroll
    for (int i = 0; i < 4; i++)
        #pragma unroll
        for (int j = 0; j < 4; j++) c[i][j] = 0.0f;

    for (int k0 = 0; k0 < R_DIM; k0 += BK) {
        #pragma unroll
        for (int l = 0; l < 2; l++) {
            int idx = tid + l * 256;          // 0..511
            int kk = idx / BM;
            int m  = idx % BM;
            int gi = k0 + kk;
            float av = 0.0f;
            if (gi < R_DIM)
                av = (gi < C_DIM) ? x[(bm0 + m) * C_DIM + gi] : 1.0f;
            As[kk][m] = av;

            int kk2 = idx / BN;
            int n   = idx % BN;
            int gi2 = k0 + kk2;
            float bv = 0.0f;
            if (gi2 < R_DIM)
                bv = mu[gi2 * C_DIM + bn0 + n];
            Bs[kk2][n] = bv;
        }
        __syncthreads();

        #pragma unroll
        for (int kk = 0; kk < BK; kk++) {
            float a[4], bb[4];
            #pragma unroll
            for (int i = 0; i < 4; i++) a[i]  = As[kk][ty * 4 + i];
            #pragma unroll
            for (int j = 0; j < 4; j++) bb[j] = Bs[kk][tx * 4 + j];
            #pragma unroll
            for (int i = 0; i < 4; i++)
                #pragma unroll
                for (int j = 0; j < 4; j++)
                    c[i][j] += a[i] * bb[j];
        }
        __syncthreads();
    }

    #pragma unroll
    for (int i = 0; i < 4; i++) {
        int gm = bm0 + ty * 4 + i;
        float4 v = make_float4(c[i][0], c[i][1], c[i][2], c[i][3]);
        *reinterpret_cast<float4*>(&g_G[gm * C_DIM + bn0 + tx * 4]) = v;
    }
}

// ---------------------------------------------------------------------------
// Kernel 3: main E-streaming kernel.
// Block = (batch b, half of output dim). 128 threads x 4 contiguous outputs.
// h[b,o] = G[b,o] + s_c[o] * sum_i y[b,i] * E[b,i,o],  y = x1 * s_r.
// E read fully coalesced as float4; y broadcast from SMEM.
// ---------------------------------------------------------------------------
__global__ __launch_bounds__(128) void main_kernel(const float* __restrict__ x,
                                                   const float* __restrict__ lv_in,
                                                   const float* __restrict__ lv_out,
                                                   const float* __restrict__ E,
                                                   float* __restrict__ out) {
    __shared__ __align__(16) float y_sh[R_DIM + 3];  // pad so float4 reads stay in-bounds

    const int b  = blockIdx.x >> 1;
    const int oh = blockIdx.x & 1;
    const int t  = threadIdx.x;

    for (int i = t; i < R_DIM; i += 128) {
        float xv = (i < C_DIM) ? x[b * C_DIM + i] : 1.0f;
        y_sh[i] = xv * expf(0.5f * lv_in[i]);
    }
    if (t < 3) y_sh[R_DIM + t] = 0.0f;
    __syncthreads();

    const int o = oh * 512 + t * 4;
    const float4* __restrict__ Ep =
        reinterpret_cast<const float4*>(E + (size_t)b * (size_t)(R_DIM * C_DIM) + o);

    float4 a0 = make_float4(0.f, 0.f, 0.f, 0.f);
    float4 a1 = make_float4(0.f, 0.f, 0.f, 0.f);
    float4 a2 = make_float4(0.f, 0.f, 0.f, 0.f);
    float4 a3 = make_float4(0.f, 0.f, 0.f, 0.f);

    const int STR = C_DIM / 4;  // 256 float4 per row

    #pragma unroll 2
    for (int i = 0; i < 1024; i += 4) {
        float4 y  = *reinterpret_cast<const float4*>(&y_sh[i]);
        float4 e0 = Ep[(i + 0) * STR];
        float4 e1 = Ep[(i + 1) * STR];
        float4 e2 = Ep[(i + 2) * STR];
        float4 e3 = Ep[(i + 3) * STR];
        a0.x += y.x * e0.x; a0.y += y.x * e0.y; a0.z += y.x * e0.z; a0.w += y.x * e0.w;
        a1.x += y.y * e1.x; a1.y += y.y * e1.y; a1.z += y.y * e1.z; a1.w += y.y * e1.w;
        a2.x += y.z * e2.x; a2.y += y.z * e2.y; a2.z += y.z * e2.z; a2.w += y.z * e2.w;
        a3.x += y.w * e3.x; a3.y += y.w * e3.y; a3.z += y.w * e3.z; a3.w += y.w * e3.w;
    }
    {   // remainder i = 1024 (bias row)
        float yv = y_sh[1024];
        float4 e = Ep[1024 * STR];
        a0.x += yv * e.x; a0.y += yv * e.y; a0.z += yv * e.z; a0.w += yv * e.w;
    }

    float4 acc = make_float4(a0.x + a1.x + a2.x + a3.x,
                             a0.y + a1.y + a2.y + a3.y,
                             a0.z + a1.z + a2.z + a3.z,
                             a0.w + a1.w + a2.w + a3.w);

    float4 sc = make_float4(expf(0.5f * lv_out[o + 0]),
                            expf(0.5f * lv_out[o + 1]),
                            expf(0.5f * lv_out[o + 2]),
                            expf(0.5f * lv_out[o + 3]));

    const float4 g = *reinterpret_cast<const float4*>(&g_G[b * C_DIM + o]);
    float4 r = make_float4(g.x + sc.x * acc.x,
                           g.y + sc.y * acc.y,
                           g.z + sc.z * acc.z,
                           g.w + sc.w * acc.w);
    *reinterpret_cast<float4*>(&out[b * C_DIM + o]) = r;
}

// ---------------------------------------------------------------------------
// Kernel 4: finalize D_KL scalar
// ---------------------------------------------------------------------------
__global__ void dkl_final_kernel(float* __restrict__ out) {
    double smu2 = 0.0;
    for (int i = 0; i < 256; i++) smu2 += g_mu2[i];
    double dkl = 0.5 * (g_lv[0] * g_lv[2] + smu2
                        - (double)R_DIM * (double)C_DIM
                        - (double)C_DIM * g_lv[1]
                        - (double)R_DIM * g_lv[3]);
    out[M_BATCH * C_DIM] = (float)dkl;
}

// ---------------------------------------------------------------------------
extern "C" void kernel_launch(void* const* d_in, const int* in_sizes, int n_in,
                              void* d_out, int out_size) {
    const float* x      = (const float*)d_in[0];
    const float* mu     = (const float*)d_in[1];
    const float* lv_in  = (const float*)d_in[2];
    const float* lv_out = (const float*)d_in[3];
    const float* E      = (const float*)d_in[4];
    float* out = (float*)d_out;

    dkl_partial_kernel<<<256, 256>>>(mu, lv_in, lv_out);
    gemm_kernel<<<dim3(C_DIM / BN, M_BATCH / BM), 256>>>(x, mu);
    main_kernel<<<M_BATCH * 2, 128>>>(x, lv_in, lv_out, E, out);
    if (out_size > M_BATCH * C_DIM) {
        dkl_final_kernel<<<1, 1>>>(out);
    }
}

// round 2
// speedup vs baseline: 1.2121x; 1.2121x over previous
#include <cuda_runtime.h>
#include <math.h>

#define M_BATCH 256
#define R_DIM   1025
#define C_DIM   1024

// Scratch (__device__ globals only — no allocation allowed)
__device__ __align__(16) float g_G[M_BATCH * C_DIM];        // X1 @ mu
__device__ __align__(16) float g_part0[M_BATCH * C_DIM];    // i in [0,512)
__device__ __align__(16) float g_part1[M_BATCH * C_DIM];    // i in [512,1025)
__device__ double g_mu2[256];
__device__ double g_lv[4];   // sum exp(lv_in), sum lv_in, sum exp(lv_out), sum lv_out

// ---------------------------------------------------------------------------
// GEMM: G = X1 @ mu   (256x1025 @ 1025x1024), 64x64 tiles, BK=8
// ---------------------------------------------------------------------------
#define BM 64
#define BN 64
#define BK 8

__global__ __launch_bounds__(256) void gemm_kernel(const float* __restrict__ x,
                                                   const float* __restrict__ mu) {
    __shared__ float As[BK][BM];
    __shared__ float Bs[BK][BN];

    const int tid = threadIdx.x;
    const int tx = tid & 15;
    const int ty = tid >> 4;
    const int bn0 = blockIdx.x * BN;
    const int bm0 = blockIdx.y * BM;

    float c[4][4];
    #pragma unroll
    for (int i = 0; i < 4; i++)
        #pragma unroll
        for (int j = 0; j < 4; j++) c[i][j] = 0.0f;

    for (int k0 = 0; k0 < R_DIM; k0 += BK) {
        #pragma unroll
        for (int l = 0; l < 2; l++) {
            int idx = tid + l * 256;
            int kk = idx / BM;
            int m  = idx % BM;
            int gi = k0 + kk;
            float av = 0.0f;
            if (gi < R_DIM)
                av = (gi < C_DIM) ? x[(bm0 + m) * C_DIM + gi] : 1.0f;
            As[kk][m] = av;

            int kk2 = idx / BN;
            int n   = idx % BN;
            int gi2 = k0 + kk2;
            float bv = 0.0f;
            if (gi2 < R_DIM)
                bv = mu[gi2 * C_DIM + bn0 + n];
            Bs[kk2][n] = bv;
        }
        __syncthreads();

        #pragma unroll
        for (int kk = 0; kk < BK; kk++) {
            float a[4], bb[4];
            #pragma unroll
            for (int i = 0; i < 4; i++) a[i]  = As[kk][ty * 4 + i];
            #pragma unroll
            for (int j = 0; j < 4; j++) bb[j] = Bs[kk][tx * 4 + j];
            #pragma unroll
            for (int i = 0; i < 4; i++)
                #pragma unroll
                for (int j = 0; j < 4; j++)
                    c[i][j] += a[i] * bb[j];
        }
        __syncthreads();
    }

    #pragma unroll
    for (int i = 0; i < 4; i++) {
        int gm = bm0 + ty * 4 + i;
        float4 v = make_float4(c[i][0], c[i][1], c[i][2], c[i][3]);
        *reinterpret_cast<float4*>(&g_G[gm * C_DIM + bn0 + tx * 4]) = v;
    }
}

// ---------------------------------------------------------------------------
// Main E-streaming kernel. Grid: (oh=2, sp=2, b=256) = 1024 blocks x 128 thr.
// All blocks co-resident (no tail wave). Each thread: 4 contiguous outputs,
// 8 rows per batch => 8 outstanding LDG.128 per thread.
// Writes raw partial sums (no scale/G — applied in combine).
// ---------------------------------------------------------------------------
__global__ __launch_bounds__(128) void main_kernel(const float* __restrict__ x,
                                                   const float* __restrict__ lv_in,
                                                   const float* __restrict__ E) {
    __shared__ __align__(16) float y_sh[R_DIM + 3];

    const int oh = blockIdx.x;
    const int sp = blockIdx.y;
    const int b  = blockIdx.z;
    const int t  = threadIdx.x;

    const int i0 = sp * 512;
    const int i1 = sp ? R_DIM : 512;

    for (int i = i0 + t; i < i1; i += 128) {
        float xv = (i < C_DIM) ? x[b * C_DIM + i] : 1.0f;
        y_sh[i] = xv * expf(0.5f * lv_in[i]);
    }
    __syncthreads();

    const int o = oh * 512 + t * 4;
    const float4* __restrict__ Ep =
        reinterpret_cast<const float4*>(E + (size_t)b * (size_t)(R_DIM * C_DIM) + o);

    float4 a0 = make_float4(0.f, 0.f, 0.f, 0.f);
    float4 a1 = make_float4(0.f, 0.f, 0.f, 0.f);
    float4 a2 = make_float4(0.f, 0.f, 0.f, 0.f);
    float4 a3 = make_float4(0.f, 0.f, 0.f, 0.f);

    const int STR = C_DIM / 4;  // 256 float4 per E row

    int i = i0;
    for (; i + 8 <= i1; i += 8) {
        // batch of 8 independent loads — keep them all outstanding
        float4 e0 = Ep[(i + 0) * STR];
        float4 e1 = Ep[(i + 1) * STR];
        float4 e2 = Ep[(i + 2) * STR];
        float4 e3 = Ep[(i + 3) * STR];
        float4 e4 = Ep[(i + 4) * STR];
        float4 e5 = Ep[(i + 5) * STR];
        float4 e6 = Ep[(i + 6) * STR];
        float4 e7 = Ep[(i + 7) * STR];
        float4 ya = *reinterpret_cast<const float4*>(&y_sh[i]);
        float4 yb = *reinterpret_cast<const float4*>(&y_sh[i + 4]);

        a0.x += ya.x * e0.x; a0.y += ya.x * e0.y; a0.z += ya.x * e0.z; a0.w += ya.x * e0.w;
        a1.x += ya.y * e1.x; a1.y += ya.y * e1.y; a1.z += ya.y * e1.z; a1.w += ya.y * e1.w;
        a2.x += ya.z * e2.x; a2.y += ya.z * e2.y; a2.z += ya.z * e2.z; a2.w += ya.z * e2.w;
        a3.x += ya.w * e3.x; a3.y += ya.w * e3.y; a3.z += ya.w * e3.z; a3.w += ya.w * e3.w;
        a0.x += yb.x * e4.x; a0.y += yb.x * e4.y; a0.z += yb.x * e4.z; a0.w += yb.x * e4.w;
        a1.x += yb.y * e5.x; a1.y += yb.y * e5.y; a1.z += yb.y * e5.z; a1.w += yb.y * e5.w;
        a2.x += yb.z * e6.x; a2.y += yb.z * e6.y; a2.z += yb.z * e6.z; a2.w += yb.z * e6.w;
        a3.x += yb.w * e7.x; a3.y += yb.w * e7.y; a3.z += yb.w * e7.z; a3.w += yb.w * e7.w;
    }
    for (; i < i1; i++) {  // remainder (bias row 1024 for sp=1)
        float yv = y_sh[i];
        float4 e = Ep[i * STR];
        a0.x += yv * e.x; a0.y += yv * e.y; a0.z += yv * e.z; a0.w += yv * e.w;
    }

    float4 acc = make_float4(a0.x + a1.x + a2.x + a3.x,
                             a0.y + a1.y + a2.y + a3.y,
                             a0.z + a1.z + a2.z + a3.z,
                             a0.w + a1.w + a2.w + a3.w);

    float* part = sp ? g_part1 : g_part0;
    *reinterpret_cast<float4*>(&part[b * C_DIM + o]) = acc;
}

// ---------------------------------------------------------------------------
// D_KL partial sums (deterministic, no atomics)
// ---------------------------------------------------------------------------
__global__ void dkl_partial_kernel(const float* __restrict__ mu,
                                   const float* __restrict__ lv_in,
                                   const float* __restrict__ lv_out) {
    __shared__ double red[256];
    const int t = threadIdx.x;
    const int b = blockIdx.x;
    const int total = R_DIM * C_DIM;

    double s = 0.0;
    for (int idx = b * 256 + t; idx < total; idx += 256 * 256) {
        float v = mu[idx];
        s += (double)v * (double)v;
    }
    red[t] = s;
    __syncthreads();
    for (int w = 128; w > 0; w >>= 1) {
        if (t < w) red[t] += red[t + w];
        __syncthreads();
    }
    if (t == 0) g_mu2[b] = red[0];

    if (b == 0) {
        double vals[4] = {0.0, 0.0, 0.0, 0.0};
        for (int i = t; i < R_DIM; i += 256) {
            float l = lv_in[i];
            vals[0] += exp((double)l);
            vals[1] += (double)l;
        }
        for (int i = t; i < C_DIM; i += 256) {
            float l = lv_out[i];
            vals[2] += exp((double)l);
            vals[3] += (double)l;
        }
        for (int j = 0; j < 4; j++) {
            __syncthreads();
            red[t] = vals[j];
            __syncthreads();
            for (int w = 128; w > 0; w >>= 1) {
                if (t < w) red[t] += red[t + w];
                __syncthreads();
            }
            if (t == 0) g_lv[j] = red[0];
        }
    }
}

// ---------------------------------------------------------------------------
// Combine: out = G + s_c * (part0 + part1). Block 0 also finalizes D_KL.
// ---------------------------------------------------------------------------
__global__ __launch_bounds__(128) void combine_kernel(const float* __restrict__ lv_out,
                                                      float* __restrict__ out,
                                                      int write_dkl) {
    const int t = threadIdx.x;
    const int idx4 = blockIdx.x * 128 + t;      // 65536 float4s total
    const int b = idx4 >> 8;
    const int o = (idx4 & 255) * 4;
    const int off = b * C_DIM + o;

    float4 p0 = *reinterpret_cast<const float4*>(&g_part0[off]);
    float4 p1 = *reinterpret_cast<const float4*>(&g_part1[off]);
    float4 g  = *reinterpret_cast<const float4*>(&g_G[off]);
    float4 sc = make_float4(expf(0.5f * lv_out[o + 0]),
                            expf(0.5f * lv_out[o + 1]),
                            expf(0.5f * lv_out[o + 2]),
                            expf(0.5f * lv_out[o + 3]));
    float4 r = make_float4(g.x + sc.x * (p0.x + p1.x),
                           g.y + sc.y * (p0.y + p1.y),
                           g.z + sc.z * (p0.z + p1.z),
                           g.w + sc.w * (p0.w + p1.w));
    *reinterpret_cast<float4*>(&out[off]) = r;

    if (write_dkl && blockIdx.x == 0) {
        __shared__ double red[128];
        red[t] = g_mu2[t] + g_mu2[t + 128];
        __syncthreads();
        for (int w = 64; w > 0; w >>= 1) {
            if (t < w) red[t] += red[t + w];
            __syncthreads();
        }
        if (t == 0) {
            double dkl = 0.5 * (g_lv[0] * g_lv[2] + red[0]
                                - (double)R_DIM * (double)C_DIM
                                - (double)C_DIM * g_lv[1]
                                - (double)R_DIM * g_lv[3]);
            out[M_BATCH * C_DIM] = (float)dkl;
        }
    }
}

// ---------------------------------------------------------------------------
extern "C" void kernel_launch(void* const* d_in, const int* in_sizes, int n_in,
                              void* d_out, int out_size) {
    const float* x      = (const float*)d_in[0];
    const float* mu     = (const float*)d_in[1];
    const float* lv_in  = (const float*)d_in[2];
    const float* lv_out = (const float*)d_in[3];
    const float* E      = (const float*)d_in[4];
    float* out = (float*)d_out;

    // Order chosen so ncu (-s 5 -c 1) lands on main_kernel (pos 1 of replay 2)
    gemm_kernel<<<dim3(C_DIM / BN, M_BATCH / BM), 256>>>(x, mu);
    main_kernel<<<dim3(2, 2, M_BATCH), 128>>>(x, lv_in, E);
    dkl_partial_kernel<<<256, 256>>>(mu, lv_in, lv_out);
    combine_kernel<<<512, 128>>>(lv_out, out, out_size > M_BATCH * C_DIM ? 1 : 0);
}

// round 3
// speedup vs baseline: 1.3002x; 1.0727x over previous
#include <cuda_runtime.h>
#include <math.h>

#define M_BATCH 256
#define R_DIM   1025
#define C_DIM   1024

// Scratch (__device__ globals only — no allocation allowed)
__device__ __align__(16) float g_G[M_BATCH * C_DIM];        // X1 @ mu
__device__ __align__(16) float g_part0[M_BATCH * C_DIM];    // i in [0,512)
__device__ __align__(16) float g_part1[M_BATCH * C_DIM];    // i in [512,1025)
__device__ double g_mu2[256];
__device__ double g_lv[4];   // sum exp(lv_in), sum lv_in, sum exp(lv_out), sum lv_out

// ---------------------------------------------------------------------------
// GEMM: G = X1 @ mu   (256x1025 @ 1025x1024), 64x64 tiles, BK=8
// ---------------------------------------------------------------------------
#define BM 64
#define BN 64
#define BK 8

__global__ __launch_bounds__(256) void gemm_kernel(const float* __restrict__ x,
                                                   const float* __restrict__ mu) {
    __shared__ float As[BK][BM];
    __shared__ float Bs[BK][BN];

    const int tid = threadIdx.x;
    const int tx = tid & 15;
    const int ty = tid >> 4;
    const int bn0 = blockIdx.x * BN;
    const int bm0 = blockIdx.y * BM;

    float c[4][4];
    #pragma unroll
    for (int i = 0; i < 4; i++)
        #pragma unroll
        for (int j = 0; j < 4; j++) c[i][j] = 0.0f;

    for (int k0 = 0; k0 < R_DIM; k0 += BK) {
        #pragma unroll
        for (int l = 0; l < 2; l++) {
            int idx = tid + l * 256;
            int kk = idx / BM;
            int m  = idx % BM;
            int gi = k0 + kk;
            float av = 0.0f;
            if (gi < R_DIM)
                av = (gi < C_DIM) ? x[(bm0 + m) * C_DIM + gi] : 1.0f;
            As[kk][m] = av;

            int kk2 = idx / BN;
            int n   = idx % BN;
            int gi2 = k0 + kk2;
            float bv = 0.0f;
            if (gi2 < R_DIM)
                bv = mu[gi2 * C_DIM + bn0 + n];
            Bs[kk2][n] = bv;
        }
        __syncthreads();

        #pragma unroll
        for (int kk = 0; kk < BK; kk++) {
            float a[4], bb[4];
            #pragma unroll
            for (int i = 0; i < 4; i++) a[i]  = As[kk][ty * 4 + i];
            #pragma unroll
            for (int j = 0; j < 4; j++) bb[j] = Bs[kk][tx * 4 + j];
            #pragma unroll
            for (int i = 0; i < 4; i++)
                #pragma unroll
                for (int j = 0; j < 4; j++)
                    c[i][j] += a[i] * bb[j];
        }
        __syncthreads();
    }

    #pragma unroll
    for (int i = 0; i < 4; i++) {
        int gm = bm0 + ty * 4 + i;
        float4 v = make_float4(c[i][0], c[i][1], c[i][2], c[i][3]);
        *reinterpret_cast<float4*>(&g_G[gm * C_DIM + bn0 + tx * 4]) = v;
    }
}

// ---------------------------------------------------------------------------
// D_KL partial sums. mu^2 accumulated in float (FP32 pipe), reduced in double.
// ---------------------------------------------------------------------------
__global__ void dkl_partial_kernel(const float* __restrict__ mu,
                                   const float* __restrict__ lv_in,
                                   const float* __restrict__ lv_out) {
    __shared__ double red[256];
    const int t = threadIdx.x;
    const int b = blockIdx.x;
    const int total = R_DIM * C_DIM;

    float s = 0.0f;
    for (int idx = b * 256 + t; idx < total; idx += 256 * 256) {
        float v = mu[idx];
        s = fmaf(v, v, s);
    }
    red[t] = (double)s;
    __syncthreads();
    for (int w = 128; w > 0; w >>= 1) {
        if (t < w) red[t] += red[t + w];
        __syncthreads();
    }
    if (t == 0) g_mu2[b] = red[0];

    if (b == 0) {
        double vals[4] = {0.0, 0.0, 0.0, 0.0};
        for (int i = t; i < R_DIM; i += 256) {
            float l = lv_in[i];
            vals[0] += (double)expf(l);
            vals[1] += (double)l;
        }
        for (int i = t; i < C_DIM; i += 256) {
            float l = lv_out[i];
            vals[2] += (double)expf(l);
            vals[3] += (double)l;
        }
        for (int j = 0; j < 4; j++) {
            __syncthreads();
            red[t] = vals[j];
            __syncthreads();
            for (int w = 128; w > 0; w >>= 1) {
                if (t < w) red[t] += red[t + w];
                __syncthreads();
            }
            if (t == 0) g_lv[j] = red[0];
        }
    }
}

// ---------------------------------------------------------------------------
// No-op spacer so ncu's fixed launch-index capture lands on main_kernel.
// ---------------------------------------------------------------------------
__global__ void noop_kernel() {}

// ---------------------------------------------------------------------------
// Main E-streaming kernel. Grid: (oh=2, sp=2, b=256) = 1024 blocks x 128 thr.
// 16 rows per batch => 16 outstanding LDG.128 (8 KB in flight per warp).
// E read with __ldcs (evict-first streaming).
// ---------------------------------------------------------------------------
__global__ __launch_bounds__(128) void main_kernel(const float* __restrict__ x,
                                                   const float* __restrict__ lv_in,
                                                   const float* __restrict__ E) {
    __shared__ __align__(16) float y_sh[R_DIM + 3];

    const int oh = blockIdx.x;
    const int sp = blockIdx.y;
    const int b  = blockIdx.z;
    const int t  = threadIdx.x;

    const int i0 = sp * 512;
    const int i1 = sp ? R_DIM : 512;

    for (int i = i0 + t; i < i1; i += 128) {
        float xv = (i < C_DIM) ? x[b * C_DIM + i] : 1.0f;
        y_sh[i] = xv * expf(0.5f * lv_in[i]);
    }
    __syncthreads();

    const int o = oh * 512 + t * 4;
    const float4* __restrict__ Ep =
        reinterpret_cast<const float4*>(E + (size_t)b * (size_t)(R_DIM * C_DIM) + o);

    float4 acc[4];
    #pragma unroll
    for (int r = 0; r < 4; r++) acc[r] = make_float4(0.f, 0.f, 0.f, 0.f);

    const int STR = C_DIM / 4;  // 256 float4 per E row

    int i = i0;
    for (; i + 16 <= i1; i += 16) {
        float4 e[16];
        #pragma unroll
        for (int r = 0; r < 16; r++)
            e[r] = __ldcs(&Ep[(i + r) * STR]);
        #pragma unroll
        for (int r = 0; r < 16; r++) {
            float yv = y_sh[i + r];
            acc[r & 3].x += yv * e[r].x;
            acc[r & 3].y += yv * e[r].y;
            acc[r & 3].z += yv * e[r].z;
            acc[r & 3].w += yv * e[r].w;
        }
    }
    for (; i < i1; i++) {  // remainder (bias row 1024 for sp=1)
        float yv = y_sh[i];
        float4 e = __ldcs(&Ep[i * STR]);
        acc[0].x += yv * e.x; acc[0].y += yv * e.y;
        acc[0].z += yv * e.z; acc[0].w += yv * e.w;
    }

    float4 r4 = make_float4(acc[0].x + acc[1].x + acc[2].x + acc[3].x,
                            acc[0].y + acc[1].y + acc[2].y + acc[3].y,
                            acc[0].z + acc[1].z + acc[2].z + acc[3].z,
                            acc[0].w + acc[1].w + acc[2].w + acc[3].w);

    float* part = sp ? g_part1 : g_part0;
    *reinterpret_cast<float4*>(&part[b * C_DIM + o]) = r4;
}

// ---------------------------------------------------------------------------
// Combine: out = G + s_c * (part0 + part1). Block 0 also finalizes D_KL.
// ---------------------------------------------------------------------------
__global__ __launch_bounds__(128) void combine_kernel(const float* __restrict__ lv_out,
                                                      float* __restrict__ out,
                                                      int write_dkl) {
    const int t = threadIdx.x;
    const int idx4 = blockIdx.x * 128 + t;      // 65536 float4s total
    const int b = idx4 >> 8;
    const int o = (idx4 & 255) * 4;
    const int off = b * C_DIM + o;

    float4 p0 = *reinterpret_cast<const float4*>(&g_part0[off]);
    float4 p1 = *reinterpret_cast<const float4*>(&g_part1[off]);
    float4 g  = *reinterpret_cast<const float4*>(&g_G[off]);
    float4 sc = make_float4(expf(0.5f * lv_out[o + 0]),
                            expf(0.5f * lv_out[o + 1]),
                            expf(0.5f * lv_out[o + 2]),
                            expf(0.5f * lv_out[o + 3]));
    float4 r = make_float4(g.x + sc.x * (p0.x + p1.x),
                           g.y + sc.y * (p0.y + p1.y),
                           g.z + sc.z * (p0.z + p1.z),
                           g.w + sc.w * (p0.w + p1.w));
    *reinterpret_cast<float4*>(&out[off]) = r;

    if (write_dkl && blockIdx.x == 0) {
        __shared__ double red[128];
        red[t] = g_mu2[t] + g_mu2[t + 128];
        __syncthreads();
        for (int w = 64; w > 0; w >>= 1) {
            if (t < w) red[t] += red[t + w];
            __syncthreads();
        }
        if (t == 0) {
            double dkl = 0.5 * (g_lv[0] * g_lv[2] + red[0]
                                - (double)R_DIM * (double)C_DIM
                                - (double)C_DIM * g_lv[1]
                                - (double)R_DIM * g_lv[3]);
            out[M_BATCH * C_DIM] = (float)dkl;
        }
    }
}

// ---------------------------------------------------------------------------
extern "C" void kernel_launch(void* const* d_in, const int* in_sizes, int n_in,
                              void* d_out, int out_size) {
    const float* x      = (const float*)d_in[0];
    const float* mu     = (const float*)d_in[1];
    const float* lv_in  = (const float*)d_in[2];
    const float* lv_out = (const float*)d_in[3];
    const float* E      = (const float*)d_in[4];
    float* out = (float*)d_out;

    // ncu has landed on launch index 3 both rounds -> put main_kernel there.
    gemm_kernel<<<dim3(C_DIM / BN, M_BATCH / BM), 256>>>(x, mu);
    dkl_partial_kernel<<<256, 256>>>(mu, lv_in, lv_out);
    noop_kernel<<<1, 32>>>();
    main_kernel<<<dim3(2, 2, M_BATCH), 128>>>(x, lv_in, E);
    combine_kernel<<<512, 128>>>(lv_out, out, out_size > M_BATCH * C_DIM ? 1 : 0);
}

// round 4
// speedup vs baseline: 2.1824x; 1.6786x over previous
#include <cuda_runtime.h>
#include <math.h>

#define M_BATCH 256
#define R_DIM   1025
#define C_DIM   1024

// Scratch (__device__ globals only — no allocation allowed)
__device__ __align__(16) float g_G[M_BATCH * C_DIM];        // X1 @ mu
__device__ __align__(16) float g_part0[M_BATCH * C_DIM];    // i in [0,512)
__device__ __align__(16) float g_part1[M_BATCH * C_DIM];    // i in [512,1025)
__device__ double g_mu2[128];
__device__ double g_lv[4];   // sum exp(lv_in), sum lv_in, sum exp(lv_out), sum lv_out

// Block partition of the fused kernel
#define NB_GEMM 128
#define NB_DKL  128
#define NB_MAIN 1024
#define NB_TOTAL (NB_GEMM + NB_DKL + NB_MAIN)

// GEMM tile
#define BM 32
#define BN 64
#define BK 8

__global__ void noop_kernel() {}

// ---------------------------------------------------------------------------
// Fused kernel: blocks [0,128) = GEMM, [128,256) = D_KL partials,
// [256,1280) = E-streaming. GEMM/DKL latency hides under the DRAM-bound
// stream blocks (stream uses <10% of issue slots).
// ---------------------------------------------------------------------------
__global__ __launch_bounds__(128) void fused_kernel(const float* __restrict__ x,
                                                    const float* __restrict__ mu,
                                                    const float* __restrict__ lv_in,
                                                    const float* __restrict__ lv_out,
                                                    const float* __restrict__ E) {
    __shared__ __align__(16) char sh_raw[4416];
    const int bid = blockIdx.x;
    const int t   = threadIdx.x;

    if (bid < NB_GEMM) {
        // ---------------- GEMM: G = X1 @ mu, 32x64 tile ----------------
        float (*As)[33] = reinterpret_cast<float (*)[33]>(sh_raw);          // 1056 B
        float (*Bs)[BN] = reinterpret_cast<float (*)[BN]>(sh_raw + 1056);   // 2048 B

        const int bn0 = (bid & 15) * BN;   // 16 N-tiles
        const int bm0 = (bid >> 4) * BM;   // 8 M-tiles
        const int tx = t & 15;
        const int ty = t >> 4;

        float c[4][4];
        #pragma unroll
        for (int i = 0; i < 4; i++)
            #pragma unroll
            for (int j = 0; j < 4; j++) c[i][j] = 0.0f;

        for (int k0 = 0; k0 < R_DIM; k0 += BK) {
            // A tile: 32x8, kk fastest for coalescing-ish reads
            #pragma unroll
            for (int p = 0; p < 2; p++) {
                int idx = t + p * 128;
                int kk = idx & 7;
                int m  = idx >> 3;
                int gi = k0 + kk;
                float av = 0.0f;
                if (gi < R_DIM)
                    av = (gi < C_DIM) ? x[(bm0 + m) * C_DIM + gi] : 1.0f;
                As[kk][m] = av;
            }
            // B tile: 8x64, n fastest (fully coalesced)
            #pragma unroll
            for (int p = 0; p < 4; p++) {
                int idx = t + p * 128;
                int n  = idx & 63;
                int kk = idx >> 6;
                int gi = k0 + kk;
                Bs[kk][n] = (gi < R_DIM) ? mu[gi * C_DIM + bn0 + n] : 0.0f;
            }
            __syncthreads();

            #pragma unroll
            for (int kk = 0; kk < BK; kk++) {
                float a[4], bb[4];
                #pragma unroll
                for (int i = 0; i < 4; i++) a[i]  = As[kk][ty * 4 + i];
                #pragma unroll
                for (int j = 0; j < 4; j++) bb[j] = Bs[kk][tx * 4 + j];
                #pragma unroll
                for (int i = 0; i < 4; i++)
                    #pragma unroll
                    for (int j = 0; j < 4; j++)
                        c[i][j] += a[i] * bb[j];
            }
            __syncthreads();
        }

        #pragma unroll
        for (int i = 0; i < 4; i++) {
            int gm = bm0 + ty * 4 + i;
            float4 v = make_float4(c[i][0], c[i][1], c[i][2], c[i][3]);
            *reinterpret_cast<float4*>(&g_G[gm * C_DIM + bn0 + tx * 4]) = v;
        }
        return;
    }

    if (bid < NB_GEMM + NB_DKL) {
        // ---------------- D_KL partial sums ----------------
        double* red = reinterpret_cast<double*>(sh_raw);  // 128 doubles
        const int db = bid - NB_GEMM;
        const int total = R_DIM * C_DIM;

        float s = 0.0f;
        for (int idx = db * 128 + t; idx < total; idx += 128 * 128) {
            float v = mu[idx];
            s = fmaf(v, v, s);
        }
        red[t] = (double)s;
        __syncthreads();
        for (int w = 64; w > 0; w >>= 1) {
            if (t < w) red[t] += red[t + w];
            __syncthreads();
        }
        if (t == 0) g_mu2[db] = red[0];

        if (db == 0) {
            double vals[4] = {0.0, 0.0, 0.0, 0.0};
            for (int i = t; i < R_DIM; i += 128) {
                float l = lv_in[i];
                vals[0] += (double)expf(l);
                vals[1] += (double)l;
            }
            for (int i = t; i < C_DIM; i += 128) {
                float l = lv_out[i];
                vals[2] += (double)expf(l);
                vals[3] += (double)l;
            }
            for (int j = 0; j < 4; j++) {
                __syncthreads();
                red[t] = vals[j];
                __syncthreads();
                for (int w = 64; w > 0; w >>= 1) {
                    if (t < w) red[t] += red[t + w];
                    __syncthreads();
                }
                if (t == 0) g_lv[j] = red[0];
            }
        }
        return;
    }

    // ---------------- E-streaming (DRAM-bound) ----------------
    {
        float* y_sh = reinterpret_cast<float*>(sh_raw);  // R_DIM+3 floats

        const int lin = bid - (NB_GEMM + NB_DKL);
        const int oh = lin & 1;
        const int sp = (lin >> 1) & 1;
        const int b  = lin >> 2;

        const int i0 = sp * 512;
        const int i1 = sp ? R_DIM : 512;

        for (int i = i0 + t; i < i1; i += 128) {
            float xv = (i < C_DIM) ? x[b * C_DIM + i] : 1.0f;
            y_sh[i] = xv * expf(0.5f * lv_in[i]);
        }
        __syncthreads();

        const int o = oh * 512 + t * 4;
        const float4* __restrict__ Ep =
            reinterpret_cast<const float4*>(E + (size_t)b * (size_t)(R_DIM * C_DIM) + o);

        float4 acc[4];
        #pragma unroll
        for (int r = 0; r < 4; r++) acc[r] = make_float4(0.f, 0.f, 0.f, 0.f);

        const int STR = C_DIM / 4;

        int i = i0;
        for (; i + 16 <= i1; i += 16) {
            float4 e[16];
            #pragma unroll
            for (int r = 0; r < 16; r++)
                e[r] = __ldcs(&Ep[(i + r) * STR]);
            #pragma unroll
            for (int r = 0; r < 16; r++) {
                float yv = y_sh[i + r];
                acc[r & 3].x += yv * e[r].x;
                acc[r & 3].y += yv * e[r].y;
                acc[r & 3].z += yv * e[r].z;
                acc[r & 3].w += yv * e[r].w;
            }
        }
        for (; i < i1; i++) {
            float yv = y_sh[i];
            float4 e = __ldcs(&Ep[i * STR]);
            acc[0].x += yv * e.x; acc[0].y += yv * e.y;
            acc[0].z += yv * e.z; acc[0].w += yv * e.w;
        }

        float4 r4 = make_float4(acc[0].x + acc[1].x + acc[2].x + acc[3].x,
                                acc[0].y + acc[1].y + acc[2].y + acc[3].y,
                                acc[0].z + acc[1].z + acc[2].z + acc[3].z,
                                acc[0].w + acc[1].w + acc[2].w + acc[3].w);

        float* part = sp ? g_part1 : g_part0;
        *reinterpret_cast<float4*>(&part[b * C_DIM + o]) = r4;
    }
}

// ---------------------------------------------------------------------------
// Combine: out = G + s_c * (part0 + part1). Block 0 also finalizes D_KL.
// ---------------------------------------------------------------------------
__global__ __launch_bounds__(128) void combine_kernel(const float* __restrict__ lv_out,
                                                      float* __restrict__ out,
                                                      int write_dkl) {
    const int t = threadIdx.x;
    const int idx4 = blockIdx.x * 128 + t;
    const int b = idx4 >> 8;
    const int o = (idx4 & 255) * 4;
    const int off = b * C_DIM + o;

    float4 p0 = *reinterpret_cast<const float4*>(&g_part0[off]);
    float4 p1 = *reinterpret_cast<const float4*>(&g_part1[off]);
    float4 g  = *reinterpret_cast<const float4*>(&g_G[off]);
    float4 sc = make_float4(expf(0.5f * lv_out[o + 0]),
                            expf(0.5f * lv_out[o + 1]),
                            expf(0.5f * lv_out[o + 2]),
                            expf(0.5f * lv_out[o + 3]));
    float4 r = make_float4(g.x + sc.x * (p0.x + p1.x),
                           g.y + sc.y * (p0.y + p1.y),
                           g.z + sc.z * (p0.z + p1.z),
                           g.w + sc.w * (p0.w + p1.w));
    *reinterpret_cast<float4*>(&out[off]) = r;

    if (write_dkl && blockIdx.x == 0) {
        __shared__ double red[128];
        red[t] = g_mu2[t];
        __syncthreads();
        for (int w = 64; w > 0; w >>= 1) {
            if (t < w) red[t] += red[t + w];
            __syncthreads();
        }
        if (t == 0) {
            double dkl = 0.5 * (g_lv[0] * g_lv[2] + red[0]
                                - (double)R_DIM * (double)C_DIM
                                - (double)C_DIM * g_lv[1]
                                - (double)R_DIM * g_lv[3]);
            out[M_BATCH * C_DIM] = (float)dkl;
        }
    }
}

// ---------------------------------------------------------------------------
extern "C" void kernel_launch(void* const* d_in, const int* in_sizes, int n_in,
                              void* d_out, int out_size) {
    const float* x      = (const float*)d_in[0];
    const float* mu     = (const float*)d_in[1];
    const float* lv_in  = (const float*)d_in[2];
    const float* lv_out = (const float*)d_in[3];
    const float* E      = (const float*)d_in[4];
    float* out = (float*)d_out;

    // ncu captures in-replay launch position 3 -> fused_kernel sits there.
    noop_kernel<<<1, 32>>>();
    noop_kernel<<<1, 32>>>();
    noop_kernel<<<1, 32>>>();
    fused_kernel<<<NB_TOTAL, 128>>>(x, mu, lv_in, lv_out, E);
    combine_kernel<<<512, 128>>>(lv_out, out, out_size > M_BATCH * C_DIM ? 1 : 0);
}

// round 5
// speedup vs baseline: 2.4297x; 1.1133x over previous
#include <cuda_runtime.h>
#include <math.h>

#define M_BATCH 256
#define R_DIM   1025
#define C_DIM   1024

// Scratch (__device__ globals only — no allocation allowed)
__device__ __align__(16) float g_G[M_BATCH * C_DIM];   // X1 @ mu
__device__ double g_mu2[128];
__device__ double g_lv[4];     // sum exp(lv_in), sum lv_in, sum exp(lv_out), sum lv_out
__device__ int    g_gemm_cnt;
__device__ int    g_dkl_cnt;

// Block partition of the fused kernel (all co-resident: 768 <= 148 SMs * >=6)
#define NB_GEMM   128
#define NB_DKL    128
#define NB_STREAM 512
#define NB_TOTAL  (NB_GEMM + NB_DKL + NB_STREAM)

// GEMM tile
#define BM 32
#define BN 64
#define BK 8

__global__ void init_kernel() { g_gemm_cnt = 0; g_dkl_cnt = 0; }
__global__ void noop_kernel() {}

// ---------------------------------------------------------------------------
// Fused kernel:
//   blocks [0,128)    : GEMM  G = X1 @ mu  (sets g_gemm_cnt when done)
//   blocks [128,256)  : D_KL partials; last-to-finish block finalizes D_KL
//   blocks [256,768)  : E-stream, full K, writes final output after spinning
//                       on g_gemm_cnt (gemm finishes ~25us, stream ~160us)
// ---------------------------------------------------------------------------
__global__ __launch_bounds__(128) void fused_kernel(const float* __restrict__ x,
                                                    const float* __restrict__ mu,
                                                    const float* __restrict__ lv_in,
                                                    const float* __restrict__ lv_out,
                                                    const float* __restrict__ E,
                                                    float* __restrict__ out,
                                                    int write_dkl) {
    __shared__ __align__(16) char sh_raw[4416];
    const int bid = blockIdx.x;
    const int t   = threadIdx.x;

    if (bid < NB_GEMM) {
        // ---------------- GEMM: G = X1 @ mu, 32x64 tile ----------------
        float (*As)[33] = reinterpret_cast<float (*)[33]>(sh_raw);          // 1056 B
        float (*Bs)[BN] = reinterpret_cast<float (*)[BN]>(sh_raw + 1056);   // 2048 B

        const int bn0 = (bid & 15) * BN;
        const int bm0 = (bid >> 4) * BM;
        const int tx = t & 15;
        const int ty = t >> 4;

        float c[4][4];
        #pragma unroll
        for (int i = 0; i < 4; i++)
            #pragma unroll
            for (int j = 0; j < 4; j++) c[i][j] = 0.0f;

        for (int k0 = 0; k0 < R_DIM; k0 += BK) {
            #pragma unroll
            for (int p = 0; p < 2; p++) {
                int idx = t + p * 128;
                int kk = idx & 7;
                int m  = idx >> 3;
                int gi = k0 + kk;
                float av = 0.0f;
                if (gi < R_DIM)
                    av = (gi < C_DIM) ? x[(bm0 + m) * C_DIM + gi] : 1.0f;
                As[kk][m] = av;
            }
            #pragma unroll
            for (int p = 0; p < 4; p++) {
                int idx = t + p * 128;
                int n  = idx & 63;
                int kk = idx >> 6;
                int gi = k0 + kk;
                Bs[kk][n] = (gi < R_DIM) ? mu[gi * C_DIM + bn0 + n] : 0.0f;
            }
            __syncthreads();

            #pragma unroll
            for (int kk = 0; kk < BK; kk++) {
                float a[4], bb[4];
                #pragma unroll
                for (int i = 0; i < 4; i++) a[i]  = As[kk][ty * 4 + i];
                #pragma unroll
                for (int j = 0; j < 4; j++) bb[j] = Bs[kk][tx * 4 + j];
                #pragma unroll
                for (int i = 0; i < 4; i++)
                    #pragma unroll
                    for (int j = 0; j < 4; j++)
                        c[i][j] += a[i] * bb[j];
            }
            __syncthreads();
        }

        #pragma unroll
        for (int i = 0; i < 4; i++) {
            int gm = bm0 + ty * 4 + i;
            float4 v = make_float4(c[i][0], c[i][1], c[i][2], c[i][3]);
            *reinterpret_cast<float4*>(&g_G[gm * C_DIM + bn0 + tx * 4]) = v;
        }

        __threadfence();
        __syncthreads();
        if (t == 0) atomicAdd(&g_gemm_cnt, 1);
        return;
    }

    if (bid < NB_GEMM + NB_DKL) {
        // ---------------- D_KL partials + last-block finalize ----------------
        double* red = reinterpret_cast<double*>(sh_raw);  // 128 doubles
        const int db = bid - NB_GEMM;
        const int total = R_DIM * C_DIM;

        float s = 0.0f;
        for (int idx = db * 128 + t; idx < total; idx += 128 * 128) {
            float v = mu[idx];
            s = fmaf(v, v, s);
        }
        red[t] = (double)s;
        __syncthreads();
        for (int w = 64; w > 0; w >>= 1) {
            if (t < w) red[t] += red[t + w];
            __syncthreads();
        }
        if (t == 0) g_mu2[db] = red[0];

        if (db == 0) {
            double vals[4] = {0.0, 0.0, 0.0, 0.0};
            for (int i = t; i < R_DIM; i += 128) {
                float l = lv_in[i];
                vals[0] += (double)expf(l);
                vals[1] += (double)l;
            }
            for (int i = t; i < C_DIM; i += 128) {
                float l = lv_out[i];
                vals[2] += (double)expf(l);
                vals[3] += (double)l;
            }
            for (int j = 0; j < 4; j++) {
                __syncthreads();
                red[t] = vals[j];
                __syncthreads();
                for (int w = 64; w > 0; w >>= 1) {
                    if (t < w) red[t] += red[t + w];
                    __syncthreads();
                }
                if (t == 0) g_lv[j] = red[0];
            }
        }

        __threadfence();
        __syncthreads();
        __shared__ int is_last;
        if (t == 0) is_last = (atomicAdd(&g_dkl_cnt, 1) == NB_DKL - 1) ? 1 : 0;
        __syncthreads();

        if (is_last && write_dkl) {
            __threadfence();  // make peers' g_mu2 / g_lv visible
            red[t] = g_mu2[t];
            __syncthreads();
            for (int w = 64; w > 0; w >>= 1) {
                if (t < w) red[t] += red[t + w];
                __syncthreads();
            }
            if (t == 0) {
                double dkl = 0.5 * (g_lv[0] * g_lv[2] + red[0]
                                    - (double)R_DIM * (double)C_DIM
                                    - (double)C_DIM * g_lv[1]
                                    - (double)R_DIM * g_lv[3]);
                out[M_BATCH * C_DIM] = (float)dkl;
            }
        }
        return;
    }

    // ---------------- E-streaming (DRAM-bound), full K per block ----------------
    {
        float* y_sh = reinterpret_cast<float*>(sh_raw);  // R_DIM floats

        const int lin = bid - (NB_GEMM + NB_DKL);
        const int oh = lin & 1;
        const int b  = lin >> 1;

        for (int i = t; i < R_DIM; i += 128) {
            float xv = (i < C_DIM) ? x[b * C_DIM + i] : 1.0f;
            y_sh[i] = xv * expf(0.5f * lv_in[i]);
        }
        __syncthreads();

        const int o = oh * 512 + t * 4;
        const float4* __restrict__ Ep =
            reinterpret_cast<const float4*>(E + (size_t)b * (size_t)(R_DIM * C_DIM) + o);

        // scale for this thread's 4 outputs (computed early, overlaps stream)
        float4 sc = make_float4(expf(0.5f * lv_out[o + 0]),
                                expf(0.5f * lv_out[o + 1]),
                                expf(0.5f * lv_out[o + 2]),
                                expf(0.5f * lv_out[o + 3]));

        float4 acc[4];
        #pragma unroll
        for (int r = 0; r < 4; r++) acc[r] = make_float4(0.f, 0.f, 0.f, 0.f);

        const int STR = C_DIM / 4;

        int i = 0;
        for (; i + 16 <= R_DIM; i += 16) {
            float4 e[16];
            #pragma unroll
            for (int r = 0; r < 16; r++)
                e[r] = __ldcs(&Ep[(i + r) * STR]);
            #pragma unroll
            for (int r = 0; r < 16; r++) {
                float yv = y_sh[i + r];
                acc[r & 3].x += yv * e[r].x;
                acc[r & 3].y += yv * e[r].y;
                acc[r & 3].z += yv * e[r].z;
                acc[r & 3].w += yv * e[r].w;
            }
        }
        for (; i < R_DIM; i++) {  // remainder (bias row 1024)
            float yv = y_sh[i];
            float4 e = __ldcs(&Ep[i * STR]);
            acc[0].x += yv * e.x; acc[0].y += yv * e.y;
            acc[0].z += yv * e.z; acc[0].w += yv * e.w;
        }

        float4 r4 = make_float4(acc[0].x + acc[1].x + acc[2].x + acc[3].x,
                                acc[0].y + acc[1].y + acc[2].y + acc[3].y,
                                acc[0].z + acc[1].z + acc[2].z + acc[3].z,
                                acc[0].w + acc[1].w + acc[2].w + acc[3].w);

        // Wait for GEMM blocks (they finish ~25us into a ~160us stream; the
        // spin virtually never iterates; all blocks co-resident => no deadlock)
        if (t == 0) {
            while (atomicAdd(&g_gemm_cnt, 0) < NB_GEMM) { }
        }
        __syncthreads();
        __threadfence();

        const float4 g = *reinterpret_cast<const float4*>(&g_G[b * C_DIM + o]);
        float4 res = make_float4(g.x + sc.x * r4.x,
                                 g.y + sc.y * r4.y,
                                 g.z + sc.z * r4.z,
                                 g.w + sc.w * r4.w);
        *reinterpret_cast<float4*>(&out[b * C_DIM + o]) = res;
    }
}

// ---------------------------------------------------------------------------
extern "C" void kernel_launch(void* const* d_in, const int* in_sizes, int n_in,
                              void* d_out, int out_size) {
    const float* x      = (const float*)d_in[0];
    const float* mu     = (const float*)d_in[1];
    const float* lv_in  = (const float*)d_in[2];
    const float* lv_out = (const float*)d_in[3];
    const float* E      = (const float*)d_in[4];
    float* out = (float*)d_out;

    // ncu captures in-replay launch position 3 -> fused_kernel sits there.
    init_kernel<<<1, 1>>>();
    noop_kernel<<<1, 32>>>();
    noop_kernel<<<1, 32>>>();
    fused_kernel<<<NB_TOTAL, 128>>>(x, mu, lv_in, lv_out, E, out,
                                    out_size > M_BATCH * C_DIM ? 1 : 0);
}